// round 4
// baseline (speedup 1.0000x reference)
#include <cuda_runtime.h>

// SGConv K=3: h = A_hat^3 x ; out = h @ W^T + b
// Fixed problem shape: N=100000, E=1600000, F_in=32, F_out=64.
// All scratch in __device__ globals (no allocations). Edge-index dtype
// (int64 vs int32) sniffed on-device since the harness may store either.

#define NN 100000
#define EE 1600000
#define F_IN 32
#define F_OUT 64

// ---- device scratch ----
__device__ __align__(16) float g_deg [NN];
__device__ __align__(16) float g_dinv[NN];
__device__ __align__(16) int   g_src [EE];
__device__ __align__(16) int   g_dst [EE];
__device__ __align__(16) float g_norm[EE];
__device__ __align__(16) float g_hA  [(size_t)NN * F_IN];
__device__ __align__(16) float g_hB  [(size_t)NN * F_IN];
__device__ int g_is64;

__device__ __forceinline__ float* buf_sel(int which) {
    return which == 0 ? g_hA : g_hB;
}

// Detect whether the edge-index buffer holds int64 or int32 values.
// If int64 (little-endian), each 8-byte word is a value in [0, NN); if the
// buffer is actually int32, interpreting as int64 fuses two random values and
// yields numbers >= 2^32 with overwhelming probability over 64 samples.
__global__ void k_detect(const void* ei) {
    const long long* e64 = (const long long*)ei;
    int ok = 1;
    for (int i = 0; i < 64; i++) {
        long long v = e64[i];
        if (v < 0 || v >= NN) { ok = 0; break; }
    }
    g_is64 = ok;
    // also: deg starts at 1.0 handled by k_init_deg
}

// deg starts at 1.0 (self-loop)
__global__ void k_init_deg() {
    int i = blockIdx.x * blockDim.x + threadIdx.x;
    if (i < NN) g_deg[i] = 1.0f;
}

// per edge: read index (either dtype), store int32 copies, count in-degree
__global__ void k_count(const void* __restrict__ ei) {
    int e = blockIdx.x * blockDim.x + threadIdx.x;
    if (e >= EE) return;
    int s, d;
    if (g_is64) {
        const long long* e64 = (const long long*)ei;
        s = (int)e64[e];
        d = (int)e64[(size_t)EE + e];
    } else {
        const int* e32 = (const int*)ei;
        s = e32[e];
        d = e32[EE + e];
    }
    // defensive clamp (should never trigger on valid input)
    if ((unsigned)s >= NN) s = 0;
    if ((unsigned)d >= NN) d = 0;
    g_src[e] = s;
    g_dst[e] = d;
    atomicAdd(&g_deg[d], 1.0f);
}

__global__ void k_dinv() {
    int i = blockIdx.x * blockDim.x + threadIdx.x;
    if (i < NN) {
        float dg = g_deg[i];
        g_dinv[i] = (dg > 0.0f) ? rsqrtf(dg) : 0.0f;
    }
}

__global__ void k_norm() {
    int e = blockIdx.x * blockDim.x + threadIdx.x;
    if (e < EE) g_norm[e] = g_dinv[g_src[e]] * g_dinv[g_dst[e]];
}

// hnew[i,:] = dinv[i]^2 * hold[i,:]  (self-loop term; initializes hnew)
__global__ void k_selfinit(const float* __restrict__ x_ext, int src_sel, int dst_sel) {
    int t = blockIdx.x * blockDim.x + threadIdx.x;
    if (t >= NN * 8) return;
    const float* hold = (src_sel < 0) ? x_ext : buf_sel(src_sel);
    float* hnew = buf_sel(dst_sel);
    int i = t >> 3, c = t & 7;
    float di = g_dinv[i];
    float s = di * di;
    float4 v = reinterpret_cast<const float4*>(hold + (size_t)i * F_IN)[c];
    v.x *= s; v.y *= s; v.z *= s; v.w *= s;
    reinterpret_cast<float4*>(hnew + (size_t)i * F_IN)[c] = v;
}

// per (edge, chunk): hnew[dst, 4c:4c+4] += norm * hold[src, 4c:4c+4]
// 8 consecutive lanes share an edge -> coalesced 128B gather per edge.
__global__ void k_scatter(const float* __restrict__ x_ext, int src_sel, int dst_sel) {
    int t = blockIdx.x * blockDim.x + threadIdx.x;
    if (t >= EE * 8) return;
    const float* hold = (src_sel < 0) ? x_ext : buf_sel(src_sel);
    float* hnew = buf_sel(dst_sel);
    int e = t >> 3, c = t & 7;
    int s = g_src[e];
    int d = g_dst[e];
    float nrm = g_norm[e];
    float4 v = reinterpret_cast<const float4*>(hold + (size_t)s * F_IN)[c];
    float* o = hnew + (size_t)d * F_IN + c * 4;
    atomicAdd(o + 0, nrm * v.x);
    atomicAdd(o + 1, nrm * v.y);
    atomicAdd(o + 2, nrm * v.z);
    atomicAdd(o + 3, nrm * v.w);
}

// out[i,:] = h[i,:] @ W^T + b   (W is [F_OUT, F_IN] row-major). h = g_hA.
__global__ void k_gemm(const float* __restrict__ W,
                       const float* __restrict__ b, float* __restrict__ out) {
    __shared__ float sW[F_OUT * F_IN];
    __shared__ float sb[F_OUT];
    for (int i = threadIdx.x; i < F_OUT * F_IN; i += blockDim.x) sW[i] = W[i];
    if (threadIdx.x < F_OUT) sb[threadIdx.x] = b[threadIdx.x];
    __syncthreads();

    int i = blockIdx.x * blockDim.x + threadIdx.x;
    if (i >= NN) return;

    float4 hr[F_IN / 4];
    const float4* hp = reinterpret_cast<const float4*>(g_hA + (size_t)i * F_IN);
#pragma unroll
    for (int c = 0; c < F_IN / 4; c++) hr[c] = hp[c];

    const float4* sW4 = reinterpret_cast<const float4*>(sW);
    float4* op = reinterpret_cast<float4*>(out + (size_t)i * F_OUT);
#pragma unroll
    for (int og = 0; og < F_OUT / 4; og++) {
        float4 acc = make_float4(sb[4 * og + 0], sb[4 * og + 1], sb[4 * og + 2], sb[4 * og + 3]);
#pragma unroll
        for (int fc = 0; fc < F_IN / 4; fc++) {
            float4 hv = hr[fc];
            float4 w0 = sW4[(4 * og + 0) * (F_IN / 4) + fc];
            float4 w1 = sW4[(4 * og + 1) * (F_IN / 4) + fc];
            float4 w2 = sW4[(4 * og + 2) * (F_IN / 4) + fc];
            float4 w3 = sW4[(4 * og + 3) * (F_IN / 4) + fc];
            acc.x += hv.x * w0.x + hv.y * w0.y + hv.z * w0.z + hv.w * w0.w;
            acc.y += hv.x * w1.x + hv.y * w1.y + hv.z * w1.z + hv.w * w1.w;
            acc.z += hv.x * w2.x + hv.y * w2.y + hv.z * w2.z + hv.w * w2.w;
            acc.w += hv.x * w3.x + hv.y * w3.y + hv.z * w3.z + hv.w * w3.w;
        }
        op[og] = acc;
    }
}

static inline int cdiv(int a, int b) { return (a + b - 1) / b; }

extern "C" void kernel_launch(void* const* d_in, const int* in_sizes, int n_in,
                              void* d_out, int out_size) {
    const float* x  = (const float*)d_in[0];
    const void*  ei = (const void*)d_in[1];
    const float* W  = (const float*)d_in[2];
    const float* b  = (const float*)d_in[3];
    float* out = (float*)d_out;

    const int T = 256;

    // normalization prep
    k_detect  <<<1, 1>>>(ei);
    k_init_deg<<<cdiv(NN, T), T>>>();
    k_count   <<<cdiv(EE, T), T>>>(ei);
    k_dinv    <<<cdiv(NN, T), T>>>();
    k_norm    <<<cdiv(EE, T), T>>>();

    // hop 1: x -> hA (buf 0)
    k_selfinit<<<cdiv(NN * 8, T), T>>>(x, -1, 0);
    k_scatter <<<cdiv(EE * 8, T), T>>>(x, -1, 0);
    // hop 2: hA -> hB (buf 1)
    k_selfinit<<<cdiv(NN * 8, T), T>>>(x, 0, 1);
    k_scatter <<<cdiv(EE * 8, T), T>>>(x, 0, 1);
    // hop 3: hB -> hA (buf 0)
    k_selfinit<<<cdiv(NN * 8, T), T>>>(x, 1, 0);
    k_scatter <<<cdiv(EE * 8, T), T>>>(x, 1, 0);

    // final linear (reads g_hA directly)
    k_gemm<<<cdiv(NN, 128), 128>>>(W, b, out);
}

// round 5
// speedup vs baseline: 2.0199x; 2.0199x over previous
#include <cuda_runtime.h>

// SGConv K=3 via CSR gather (pull) hops: h = A_hat^3 x ; out = h @ W^T + b
// Fixed shape: N=100000, E=1600000, F_in=32, F_out=64.
// CSR-by-destination built once (count -> scan -> fill), then 3 atomic-free
// gather hops (warp per node, lane per feature), then fused linear.

#define NN 100000
#define EE 1600000
#define F_IN 32
#define F_OUT 64
#define SCAN_B 512
#define NBLK ((NN + SCAN_B - 1) / SCAN_B)

// ---- device scratch ----
__device__ __align__(16) int   g_degi    [NN];     // in-degree (excl. self-loop)
__device__ __align__(16) int   g_rowstart[NN];     // CSR row offsets (exclusive scan)
__device__ __align__(16) int   g_cursor  [NN];     // fill cursors
__device__ __align__(16) int   g_blksum  [NBLK];
__device__ __align__(16) int   g_blkoff  [NBLK];
__device__ __align__(16) float g_dinv    [NN];
__device__ __align__(16) int   g_src     [EE];
__device__ __align__(16) int   g_dst     [EE];
__device__ __align__(16) int   g_csr_src [EE];
__device__ __align__(16) float g_csr_norm[EE];
__device__ __align__(16) float g_hA      [(size_t)NN * F_IN];
__device__ __align__(16) float g_hB      [(size_t)NN * F_IN];
__device__ int g_is64;

__device__ __forceinline__ float* buf_sel(int which) {
    return which == 0 ? g_hA : g_hB;
}

// int64 vs int32 edge-index sniffer (int64 values are all < NN; fused int32
// pairs read as int64 are >= 2^32 with overwhelming probability).
__global__ void k_detect(const void* ei) {
    const long long* e64 = (const long long*)ei;
    int ok = 1;
    for (int i = 0; i < 64; i++) {
        long long v = e64[i];
        if (v < 0 || v >= NN) { ok = 0; break; }
    }
    g_is64 = ok;
}

__global__ void k_zero() {
    int i = blockIdx.x * blockDim.x + threadIdx.x;
    if (i < NN) { g_degi[i] = 0; g_cursor[i] = 0; }
}

// per edge: decode indices, stash int32 copies, count in-degree at dst
__global__ void k_count(const void* __restrict__ ei) {
    int e = blockIdx.x * blockDim.x + threadIdx.x;
    if (e >= EE) return;
    int s, d;
    if (g_is64) {
        const long long* e64 = (const long long*)ei;
        s = (int)e64[e];
        d = (int)e64[(size_t)EE + e];
    } else {
        const int* e32 = (const int*)ei;
        s = e32[e];
        d = e32[EE + e];
    }
    if ((unsigned)s >= NN) s = 0;
    if ((unsigned)d >= NN) d = 0;
    g_src[e] = s;
    g_dst[e] = d;
    atomicAdd(&g_degi[d], 1);
}

__global__ void k_dinv() {
    int i = blockIdx.x * blockDim.x + threadIdx.x;
    if (i < NN) g_dinv[i] = rsqrtf((float)(g_degi[i] + 1));  // +1 self-loop, always > 0
}

// block-level inclusive scan of g_degi -> exclusive offsets + block sums
__global__ void k_scan1() {
    __shared__ int sh[SCAN_B];
    int tid = threadIdx.x;
    int i = blockIdx.x * SCAN_B + tid;
    int v = (i < NN) ? g_degi[i] : 0;
    sh[tid] = v;
    __syncthreads();
#pragma unroll
    for (int off = 1; off < SCAN_B; off <<= 1) {
        int t = (tid >= off) ? sh[tid - off] : 0;
        __syncthreads();
        sh[tid] += t;
        __syncthreads();
    }
    if (i < NN) g_rowstart[i] = sh[tid] - v;  // exclusive
    if (tid == SCAN_B - 1) g_blksum[blockIdx.x] = sh[tid];
}

// scan the block sums (tiny: NBLK=196, single thread)
__global__ void k_scan2() {
    int run = 0;
    for (int b = 0; b < NBLK; b++) { g_blkoff[b] = run; run += g_blksum[b]; }
}

__global__ void k_scan3() {
    int i = blockIdx.x * blockDim.x + threadIdx.x;
    if (i < NN) g_rowstart[i] += g_blkoff[i / SCAN_B];
}

// per edge: place (src, norm) into the dst's CSR slot
__global__ void k_fill() {
    int e = blockIdx.x * blockDim.x + threadIdx.x;
    if (e >= EE) return;
    int s = g_src[e];
    int d = g_dst[e];
    int pos = g_rowstart[d] + atomicAdd(&g_cursor[d], 1);
    g_csr_src[pos]  = s;
    g_csr_norm[pos] = g_dinv[s] * g_dinv[d];
}

// gather hop: one warp per node, lane = feature column. No atomics.
__global__ void k_gather(const float* __restrict__ x_ext, int src_sel, int dst_sel) {
    int t = blockIdx.x * blockDim.x + threadIdx.x;
    int node = t >> 5;
    int lane = t & 31;
    if (node >= NN) return;
    const float* __restrict__ hold = (src_sel < 0) ? x_ext : buf_sel(src_sel);
    float* __restrict__ hnew = buf_sel(dst_sel);

    float di = g_dinv[node];
    float acc = di * di * hold[(size_t)node * F_IN + lane];  // self-loop term

    int beg = g_rowstart[node];
    int end = beg + g_degi[node];
    int e = beg;
    // 4-way unroll for memory-level parallelism on the L2 gathers
    for (; e + 3 < end; e += 4) {
        int   s0 = g_csr_src[e + 0], s1 = g_csr_src[e + 1];
        int   s2 = g_csr_src[e + 2], s3 = g_csr_src[e + 3];
        float n0 = g_csr_norm[e + 0], n1 = g_csr_norm[e + 1];
        float n2 = g_csr_norm[e + 2], n3 = g_csr_norm[e + 3];
        float v0 = hold[(size_t)s0 * F_IN + lane];
        float v1 = hold[(size_t)s1 * F_IN + lane];
        float v2 = hold[(size_t)s2 * F_IN + lane];
        float v3 = hold[(size_t)s3 * F_IN + lane];
        acc += n0 * v0;
        acc += n1 * v1;
        acc += n2 * v2;
        acc += n3 * v3;
    }
    for (; e < end; e++) {
        acc += g_csr_norm[e] * hold[(size_t)g_csr_src[e] * F_IN + lane];
    }
    hnew[(size_t)node * F_IN + lane] = acc;
}

// out[i,:] = h[i,:] @ W^T + b   (W is [F_OUT, F_IN] row-major). h = g_hA.
__global__ void k_gemm(const float* __restrict__ W,
                       const float* __restrict__ b, float* __restrict__ out) {
    __shared__ float sW[F_OUT * F_IN];
    __shared__ float sb[F_OUT];
    for (int i = threadIdx.x; i < F_OUT * F_IN; i += blockDim.x) sW[i] = W[i];
    if (threadIdx.x < F_OUT) sb[threadIdx.x] = b[threadIdx.x];
    __syncthreads();

    int i = blockIdx.x * blockDim.x + threadIdx.x;
    if (i >= NN) return;

    float4 hr[F_IN / 4];
    const float4* hp = reinterpret_cast<const float4*>(g_hA + (size_t)i * F_IN);
#pragma unroll
    for (int c = 0; c < F_IN / 4; c++) hr[c] = hp[c];

    const float4* sW4 = reinterpret_cast<const float4*>(sW);
    float4* op = reinterpret_cast<float4*>(out + (size_t)i * F_OUT);
#pragma unroll
    for (int og = 0; og < F_OUT / 4; og++) {
        float4 acc = make_float4(sb[4 * og + 0], sb[4 * og + 1], sb[4 * og + 2], sb[4 * og + 3]);
#pragma unroll
        for (int fc = 0; fc < F_IN / 4; fc++) {
            float4 hv = hr[fc];
            float4 w0 = sW4[(4 * og + 0) * (F_IN / 4) + fc];
            float4 w1 = sW4[(4 * og + 1) * (F_IN / 4) + fc];
            float4 w2 = sW4[(4 * og + 2) * (F_IN / 4) + fc];
            float4 w3 = sW4[(4 * og + 3) * (F_IN / 4) + fc];
            acc.x += hv.x * w0.x + hv.y * w0.y + hv.z * w0.z + hv.w * w0.w;
            acc.y += hv.x * w1.x + hv.y * w1.y + hv.z * w1.z + hv.w * w1.w;
            acc.z += hv.x * w2.x + hv.y * w2.y + hv.z * w2.z + hv.w * w2.w;
            acc.w += hv.x * w3.x + hv.y * w3.y + hv.z * w3.z + hv.w * w3.w;
        }
        op[og] = acc;
    }
}

static inline int cdiv(int a, int b) { return (a + b - 1) / b; }

extern "C" void kernel_launch(void* const* d_in, const int* in_sizes, int n_in,
                              void* d_out, int out_size) {
    const float* x  = (const float*)d_in[0];
    const void*  ei = (const void*)d_in[1];
    const float* W  = (const float*)d_in[2];
    const float* b  = (const float*)d_in[3];
    float* out = (float*)d_out;

    const int T = 256;

    // CSR build + normalization
    k_detect<<<1, 1>>>(ei);
    k_zero  <<<cdiv(NN, T), T>>>();
    k_count <<<cdiv(EE, T), T>>>(ei);
    k_dinv  <<<cdiv(NN, T), T>>>();
    k_scan1 <<<NBLK, SCAN_B>>>();
    k_scan2 <<<1, 1>>>();
    k_scan3 <<<cdiv(NN, T), T>>>();
    k_fill  <<<cdiv(EE, T), T>>>();

    // 3 gather hops (warp per node)
    int gthreads = NN * 32;
    k_gather<<<cdiv(gthreads, T), T>>>(x, -1, 0);  // x  -> hA
    k_gather<<<cdiv(gthreads, T), T>>>(x,  0, 1);  // hA -> hB
    k_gather<<<cdiv(gthreads, T), T>>>(x,  1, 0);  // hB -> hA

    // final linear
    k_gemm<<<cdiv(NN, 128), 128>>>(W, b, out);
}